// round 2
// baseline (speedup 1.0000x reference)
#include <cuda_runtime.h>
#include <cuda_bf16.h>

#define N_NODES 50000
#define N_EDGES 800000
#define D 128

// Scratch for h = x @ W  (25.6 MB) — __device__ global per allocation rules.
__device__ float g_H[N_NODES * D];

// ---------------------------------------------------------------------------
// GEMM: H[N_NODES, 128] = X[N_NODES, 128] @ W[128, 128]
// BM=64, BN=128 (full), BK=16. 256 threads, each computes 8x4 outputs.
// ---------------------------------------------------------------------------
#define BM 64
#define BK 16

__global__ void gemm_kernel(const float* __restrict__ X,
                            const float* __restrict__ W) {
    __shared__ float sX[BM][BK];
    __shared__ float sW[BK][D];

    const int block_m = blockIdx.x * BM;
    const int tid = threadIdx.x;           // 0..255
    const int tn = tid & 31;               // col group: cols tn*4 .. tn*4+3
    const int tm = tid >> 5;               // row group: rows tm*8 .. tm*8+7

    float acc[8][4];
#pragma unroll
    for (int i = 0; i < 8; i++)
#pragma unroll
        for (int j = 0; j < 4; j++) acc[i][j] = 0.f;

    for (int k0 = 0; k0 < D; k0 += BK) {
        // Load X tile 64x16 (1024 floats): 256 threads x 1 float4
        {
            int r = tid >> 2;               // 0..63
            int c = (tid & 3) * 4;          // 0,4,8,12
            int gm = block_m + r;
            float4 xv = make_float4(0.f, 0.f, 0.f, 0.f);
            if (gm < N_NODES)
                xv = *(const float4*)&X[gm * D + k0 + c];
            *(float4*)&sX[r][c] = xv;
        }
        // Load W tile 16x128 (2048 floats): 256 threads x 2 float4
        {
            const float4* Wv = (const float4*)&W[k0 * D];
            float4* sWv = (float4*)&sW[0][0];
            sWv[tid]       = Wv[tid];
            sWv[tid + 256] = Wv[tid + 256];
        }
        __syncthreads();

#pragma unroll
        for (int k = 0; k < BK; k++) {
            float b[4];
#pragma unroll
            for (int j = 0; j < 4; j++) b[j] = sW[k][tn * 4 + j];
#pragma unroll
            for (int i = 0; i < 8; i++) {
                float a = sX[tm * 8 + i][k];
#pragma unroll
                for (int j = 0; j < 4; j++) acc[i][j] += a * b[j];
            }
        }
        __syncthreads();
    }

#pragma unroll
    for (int i = 0; i < 8; i++) {
        int gm = block_m + tm * 8 + i;
        if (gm < N_NODES) {
            *(float4*)&g_H[gm * D + tn * 4] =
                make_float4(acc[i][0], acc[i][1], acc[i][2], acc[i][3]);
        }
    }
}

// ---------------------------------------------------------------------------
// Init: out[i][d] = bias[d]   (so the scatter can atomicAdd directly)
// ---------------------------------------------------------------------------
__global__ void init_kernel(const float* __restrict__ bias,
                            float* __restrict__ out) {
    int idx = blockIdx.x * blockDim.x + threadIdx.x;   // float4 index
    const int total = N_NODES * D / 4;
    if (idx >= total) return;
    int d4 = (idx & (D / 4 - 1)) * 4;                  // column base within row
    float4 b = *(const float4*)&bias[d4];
    ((float4*)out)[idx] = b;
}

// ---------------------------------------------------------------------------
// Scatter: for each edge e, out[row[e]] += vals[e] * H[col[e]]
// One warp per edge; each lane handles 4 consecutive floats:
// float4 gather from g_H, one vectorized red.global.add.v4.f32 scatter.
// ---------------------------------------------------------------------------
__device__ __forceinline__ void red_add_v4(float* ptr, float a, float b,
                                           float c, float d) {
    asm volatile("red.global.add.v4.f32 [%0], {%1, %2, %3, %4};"
                 :: "l"(ptr), "f"(a), "f"(b), "f"(c), "f"(d)
                 : "memory");
}

__global__ void scatter_kernel(const float* __restrict__ vals,
                               const int* __restrict__ row,
                               const int* __restrict__ col,
                               float* __restrict__ out) {
    unsigned gtid = blockIdx.x * blockDim.x + threadIdx.x;
    unsigned e = gtid >> 5;
    if (e >= N_EDGES) return;
    int lane = threadIdx.x & 31;

    int r = __ldg(&row[e]);
    int c = __ldg(&col[e]);
    float v = __ldg(&vals[e]);

    float4 h = *(const float4*)&g_H[(size_t)c * D + lane * 4];
    float* o = &out[(size_t)r * D + lane * 4];
    red_add_v4(o, v * h.x, v * h.y, v * h.z, v * h.w);
}

// ---------------------------------------------------------------------------
// ReLU epilogue
// ---------------------------------------------------------------------------
__global__ void relu_kernel(float* __restrict__ out) {
    int idx = blockIdx.x * blockDim.x + threadIdx.x;   // float4 index
    const int total = N_NODES * D / 4;
    if (idx >= total) return;
    float4 v = ((float4*)out)[idx];
    v.x = fmaxf(v.x, 0.f);
    v.y = fmaxf(v.y, 0.f);
    v.z = fmaxf(v.z, 0.f);
    v.w = fmaxf(v.w, 0.f);
    ((float4*)out)[idx] = v;
}

// ---------------------------------------------------------------------------
// Launch
// ---------------------------------------------------------------------------
extern "C" void kernel_launch(void* const* d_in, const int* in_sizes, int n_in,
                              void* d_out, int out_size) {
    const float* x      = (const float*)d_in[0];   // [50000,128]
    const float* weight = (const float*)d_in[1];   // [128,128]
    const float* bias   = (const float*)d_in[2];   // [128]
    const float* vals   = (const float*)d_in[3];   // [800000]
    const int*   row    = (const int*)d_in[4];     // [800000]
    const int*   col    = (const int*)d_in[5];     // [800000]
    float* out = (float*)d_out;                    // [50000,128]

    // 1) H = X @ W
    int gemm_blocks = (N_NODES + BM - 1) / BM;     // 782
    gemm_kernel<<<gemm_blocks, 256>>>(x, weight);

    // 2) out = bias (broadcast per row)
    int init_threads = N_NODES * D / 4;            // 1.6M float4 stores
    init_kernel<<<(init_threads + 255) / 256, 256>>>(bias, out);

    // 3) vectorized-atomic scatter
    long long scatter_threads = (long long)N_EDGES * 32;   // 25.6M
    int scatter_blocks = (int)((scatter_threads + 255) / 256);
    scatter_kernel<<<scatter_blocks, 256>>>(vals, row, col, out);

    // 4) ReLU
    relu_kernel<<<(init_threads + 255) / 256, 256>>>(out);
}